// round 9
// baseline (speedup 1.0000x reference)
#include <cuda_runtime.h>

#define NN 100000
#define EE 3200000
#define FIN 512
#define HID 16
#define CC 40
#define NB 391          // ceil(NN/256) scan blocks

// ---------------- scratch (static device globals) -----------------------------
__device__ float  g_dis[NN];
__device__ int    g_cnt[NN];
__device__ int    g_base[NN];      // exclusive scan; mutated to row-ends by scatter
__device__ int    g_bsum[NB];
__device__ int    g_bsumx[NB];
__device__ unsigned long long g_wz[256 * 16];  // W1 k-pair-zipped: [k/2][f]
__device__ int2   g_edge[EE];      // dest-sorted (src, weight-as-int)
__device__ float4 g_h1[NN * 4];    // h1 = x@W1, [N,16] as [N,4] float4
__device__ float4 g_agg1[NN * 4];  // layer-1 aggregation
__device__ float4 g_agg2[NN * 4];  // layer-2 aggregation (16-dim, pre-W2)

#define FMA2(d, a, b) asm("fma.rn.f32x2 %0, %1, %2, %0;" : "+l"(d) : "l"(a), "l"(b))
#define ZIP(d, a, b)  asm("mov.b64 %0, {%1, %2};" : "=l"(d) : "f"(a), "f"(b))
#define CPA16(s, g)   asm volatile("cp.async.cg.shared.global [%0], [%1], 16;" :: "r"(s), "l"(g))
#define CP_COMMIT()   asm volatile("cp.async.commit_group;")
#define CP_WAIT(n)    asm volatile("cp.async.wait_group %0;" :: "n"(n))

// ---------------- zero init ---------------------------------------------------
__global__ void zero_kernel() {
    int i = blockIdx.x * blockDim.x + threadIdx.x;
    if (i < NN) g_cnt[i] = 0;
}

// ---------------- in-degree count ---------------------------------------------
__global__ void count_kernel(const int* __restrict__ ei) {
    int e = blockIdx.x * blockDim.x + threadIdx.x;
    if (e >= EE) return;
    atomicAdd(&g_cnt[ei[EE + e]], 1);
}

// ---------------- W1 zip: g_wz[k2*16+f] = (W1[2k2][f], W1[2k2+1][f]) ----------
__global__ void wzip_kernel(const float* __restrict__ W1) {
    int i = blockIdx.x * blockDim.x + threadIdx.x;
    if (i >= 256 * 16) return;
    int k2 = i >> 4, f = i & 15;
    unsigned long long z;
    ZIP(z, W1[(2 * k2) * 16 + f], W1[(2 * k2 + 1) * 16 + f]);
    g_wz[i] = z;
}

// ---------------- 3-kernel exclusive scan of g_cnt -> g_base ------------------
__global__ void scanA_kernel() {
    __shared__ int s[256];
    int tid = threadIdx.x;
    int i = blockIdx.x * 256 + tid;
    int v = (i < NN) ? g_cnt[i] : 0;
    s[tid] = v;
    __syncthreads();
    for (int off = 1; off < 256; off <<= 1) {
        int t = (tid >= off) ? s[tid - off] : 0;
        __syncthreads();
        s[tid] += t;
        __syncthreads();
    }
    if (i < NN) g_base[i] = s[tid] - v;          // exclusive, intra-block
    if (tid == 255) g_bsum[blockIdx.x] = s[255];
}

__global__ void scanB_kernel() {
    __shared__ int s[512];
    int tid = threadIdx.x;
    int v = (tid < NB) ? g_bsum[tid] : 0;
    s[tid] = v;
    __syncthreads();
    for (int off = 1; off < 512; off <<= 1) {
        int t = (tid >= off) ? s[tid - off] : 0;
        __syncthreads();
        s[tid] += t;
        __syncthreads();
    }
    if (tid < NB) g_bsumx[tid] = s[tid] - v;     // exclusive block offsets
}

__global__ void scanC_kernel() {
    int i = blockIdx.x * blockDim.x + threadIdx.x;
    if (i < NN) g_base[i] += g_bsumx[i >> 8];
}

// ---------------- scatter edges (src, w); bumps g_base to row-end -------------
__global__ void scatter_kernel(const int* __restrict__ ei,
                               const float* __restrict__ w) {
    int e = blockIdx.x * blockDim.x + threadIdx.x;
    if (e >= EE) return;
    int r = ei[e];
    int c = ei[EE + e];
    int pos = atomicAdd(&g_base[c], 1);
    g_edge[pos] = make_int2(r, __float_as_int(w[e]));
}

// ---------------- weighted degree + dis via CSR gather (no atomics) -----------
__global__ void __launch_bounds__(256) degdis_kernel() {
    int node = (blockIdx.x * 256 + threadIdx.x) >> 5;
    if (node >= NN) return;
    int lane = threadIdx.x & 31;
    int b0 = node ? g_base[node - 1] : 0;   // after scatter: base[c] = row end
    int b1 = g_base[node];
    float s = 0.f;
    for (int i = b0 + lane; i < b1; i += 32) s += __int_as_float(g_edge[i].y);
#pragma unroll
    for (int m = 16; m >= 1; m >>= 1) s += __shfl_xor_sync(0xffffffffu, s, m);
    if (lane == 0) g_dis[node] = (s > 0.f) ? rsqrtf(s) : 0.f;
}

// ---------------- GEMM1 v4: h1 = x @ W1 ---------------------------------------
// 128 threads: 16 ng x 8 fg (2 f each). Tile 128 nodes. Thread: 8 nodes x 2 f.
// W pre-zipped in gmem (k-pairs) -> no zip movs in loop. 3-stage cp.async.
#define KCH 16
#define NCHUNK (FIN / KCH)   // 32
__global__ void __launch_bounds__(128) gemm1_kernel(const float* __restrict__ x) {
    __shared__ float4 xs[3][128 * 5];                 // [stage][node*5 + kq]
    __shared__ unsigned long long wsm[3][8 * 16];     // [stage][kp*16 + f]
    int tid = threadIdx.x;
    int ng = tid & 15;
    int fg = tid >> 4;                   // 0..7 -> f = 2*fg, 2*fg+1
    int nodeBase = blockIdx.x * 128;

    // cp.async coords: 512 data f4 per stage, 128 threads -> 4 each
    int xnl = tid >> 2;                  // node-local base (plus 32*s)
    int xkq = tid & 3;

    unsigned long long acc[8][2];
#pragma unroll
    for (int i = 0; i < 8; ++i) { acc[i][0] = 0ull; acc[i][1] = 0ull; }

    const float* xg = x + (size_t)xkq * 4;

#define LOAD_CHUNK(kc, buf)                                                        \
    {                                                                              \
        int kb_ = (kc) * KCH;                                                      \
        _Pragma("unroll")                                                          \
        for (int s_ = 0; s_ < 4; ++s_) {                                           \
            int nl_ = xnl + 32 * s_;                                               \
            int node_ = nodeBase + nl_; if (node_ >= NN) node_ = NN - 1;           \
            unsigned d_ = (unsigned)__cvta_generic_to_shared(&xs[buf][nl_ * 5 + xkq]); \
            CPA16(d_, xg + (size_t)node_ * FIN + kb_);                             \
        }                                                                          \
        if (tid < 64) {                                                            \
            unsigned dw_ = (unsigned)__cvta_generic_to_shared(&wsm[buf][tid * 2]); \
            CPA16(dw_, &g_wz[(kc) * 128 + tid * 2]);                               \
        }                                                                          \
        CP_COMMIT();                                                               \
    }

    LOAD_CHUNK(0, 0)
    LOAD_CHUNK(1, 1)

    for (int kc = 0; kc < NCHUNK; ++kc) {
        int cur = kc % 3;
        if (kc + 2 < NCHUNK) {
            LOAD_CHUNK(kc + 2, (kc + 2) % 3)
            CP_WAIT(2);
        } else if (kc + 1 < NCHUNK) {
            CP_WAIT(1);
        } else {
            CP_WAIT(0);
        }
        __syncthreads();

#pragma unroll
        for (int kq = 0; kq < 4; ++kq) {
            // wA: k-pair 2kq (k=4kq,4kq+1), wB: k-pair 2kq+1 (k=4kq+2,4kq+3)
            ulonglong2 wA = *(const ulonglong2*)&wsm[cur][(2 * kq) * 16 + 2 * fg];
            ulonglong2 wB = *(const ulonglong2*)&wsm[cur][(2 * kq + 1) * 16 + 2 * fg];
#pragma unroll
            for (int i = 0; i < 8; ++i) {
                ulonglong2 xu = *(const ulonglong2*)&xs[cur][(ng + 16 * i) * 5 + kq];
                FMA2(acc[i][0], xu.x, wA.x);
                FMA2(acc[i][1], xu.x, wA.y);
                FMA2(acc[i][0], xu.y, wB.x);
                FMA2(acc[i][1], xu.y, wB.y);
            }
        }
        __syncthreads();
    }

    // fold k-split halves; store float2 per node (f = 2fg, 2fg+1)
    float* h1 = (float*)g_h1;
#pragma unroll
    for (int i = 0; i < 8; ++i) {
        int node = nodeBase + ng + 16 * i;
        if (node >= NN) continue;
        float lo, hi;
        float2 o;
        asm("mov.b64 {%0, %1}, %2;" : "=f"(lo), "=f"(hi) : "l"(acc[i][0])); o.x = lo + hi;
        asm("mov.b64 {%0, %1}, %2;" : "=f"(lo), "=f"(hi) : "l"(acc[i][1])); o.y = lo + hi;
        *(float2*)&h1[node * 16 + 2 * fg] = o;
    }
}

// ---------------- gather-reduce propagation (warp per node, no atomics) -------
__global__ void __launch_bounds__(256) gather1_kernel() {
    int node = (blockIdx.x * 256 + threadIdx.x) >> 5;
    if (node >= NN) return;
    int lane = threadIdx.x & 31;
    int q = lane & 3;
    int es = lane >> 2;
    float dc = g_dis[node];
    int b0 = node ? g_base[node - 1] : 0;
    int b1e = g_base[node];
    float4 acc = make_float4(0.f, 0.f, 0.f, 0.f);
    for (int i = b0 + es; i < b1e; i += 8) {
        int2 ew = g_edge[i];
        float nw = g_dis[ew.x] * __int_as_float(ew.y) * dc;
        float4 v = g_h1[ew.x * 4 + q];
        acc.x += nw * v.x; acc.y += nw * v.y;
        acc.z += nw * v.z; acc.w += nw * v.w;
    }
#pragma unroll
    for (int m = 16; m >= 4; m >>= 1) {
        acc.x += __shfl_xor_sync(0xffffffffu, acc.x, m);
        acc.y += __shfl_xor_sync(0xffffffffu, acc.y, m);
        acc.z += __shfl_xor_sync(0xffffffffu, acc.z, m);
        acc.w += __shfl_xor_sync(0xffffffffu, acc.w, m);
    }
    if (es == 0) g_agg1[node * 4 + q] = acc;
}

// layer 2: gather relu(agg1[src] + b1) * norm
__global__ void __launch_bounds__(256) gather2_kernel(const float* __restrict__ b1) {
    int node = (blockIdx.x * 256 + threadIdx.x) >> 5;
    if (node >= NN) return;
    int lane = threadIdx.x & 31;
    int q = lane & 3;
    int es = lane >> 2;
    float4 b = ((const float4*)b1)[q];
    float dc = g_dis[node];
    int b0 = node ? g_base[node - 1] : 0;
    int b1e = g_base[node];
    float4 acc = make_float4(0.f, 0.f, 0.f, 0.f);
    for (int i = b0 + es; i < b1e; i += 8) {
        int2 ew = g_edge[i];
        float nw = g_dis[ew.x] * __int_as_float(ew.y) * dc;
        float4 v = g_agg1[ew.x * 4 + q];
        acc.x += nw * fmaxf(v.x + b.x, 0.f);
        acc.y += nw * fmaxf(v.y + b.y, 0.f);
        acc.z += nw * fmaxf(v.z + b.z, 0.f);
        acc.w += nw * fmaxf(v.w + b.w, 0.f);
    }
#pragma unroll
    for (int m = 16; m >= 4; m >>= 1) {
        acc.x += __shfl_xor_sync(0xffffffffu, acc.x, m);
        acc.y += __shfl_xor_sync(0xffffffffu, acc.y, m);
        acc.z += __shfl_xor_sync(0xffffffffu, acc.z, m);
        acc.w += __shfl_xor_sync(0xffffffffu, acc.w, m);
    }
    if (es == 0) g_agg2[node * 4 + q] = acc;
}

// ---------------- epilogue: out = log_softmax(agg2 @ W2 + b2) -----------------
__global__ void __launch_bounds__(256) out_kernel(const float* __restrict__ W2,
                                                  const float* __restrict__ b2,
                                                  float* __restrict__ out) {
    __shared__ float w2s[HID * CC];
    __shared__ float b2s[CC];
    int tid = threadIdx.x;
    for (int i = tid; i < HID * CC; i += 256) w2s[i] = W2[i];
    if (tid < CC) b2s[tid] = b2[tid];
    __syncthreads();

    int n = blockIdx.x * blockDim.x + tid;
    if (n >= NN) return;

    float a[16];
    float4* ap = (float4*)a;
    ap[0] = g_agg2[n * 4 + 0];
    ap[1] = g_agg2[n * 4 + 1];
    ap[2] = g_agg2[n * 4 + 2];
    ap[3] = g_agg2[n * 4 + 3];

    float logit[CC];
    float mx = -1e30f;
#pragma unroll
    for (int j = 0; j < CC; ++j) {
        float s = b2s[j];
#pragma unroll
        for (int i = 0; i < 16; ++i) s += a[i] * w2s[i * CC + j];
        logit[j] = s;
        mx = fmaxf(mx, s);
    }
    float sum = 0.f;
#pragma unroll
    for (int j = 0; j < CC; ++j) sum += expf(logit[j] - mx);
    float lse = mx + logf(sum);
#pragma unroll
    for (int j = 0; j < CC; ++j) out[(size_t)n * CC + j] = logit[j] - lse;
}

// ---------------- launch ------------------------------------------------------
extern "C" void kernel_launch(void* const* d_in, const int* in_sizes, int n_in,
                              void* d_out, int out_size) {
    const float* x  = (const float*)d_in[0];
    const int*   ei = (const int*)d_in[1];
    const float* w  = (const float*)d_in[2];
    const float* W1 = (const float*)d_in[3];
    const float* b1 = (const float*)d_in[4];
    const float* W2 = (const float*)d_in[5];
    const float* b2 = (const float*)d_in[6];
    float*       out = (float*)d_out;

    zero_kernel<<<(NN + 255) / 256, 256>>>();
    count_kernel<<<(EE + 255) / 256, 256>>>(ei);
    wzip_kernel<<<16, 256>>>(W1);
    gemm1_kernel<<<(NN + 127) / 128, 128>>>(x);      // 4th launch -> profiled
    scanA_kernel<<<NB, 256>>>();
    scanB_kernel<<<1, 512>>>();
    scanC_kernel<<<(NN + 255) / 256, 256>>>();
    scatter_kernel<<<(EE + 255) / 256, 256>>>(ei, w);
    degdis_kernel<<<(NN * 32 + 255) / 256, 256>>>();
    gather1_kernel<<<(NN * 32 + 255) / 256, 256>>>();
    gather2_kernel<<<(NN * 32 + 255) / 256, 256>>>(b1);
    out_kernel<<<(NN + 255) / 256, 256>>>(W2, b2, out);
}

// round 10
// speedup vs baseline: 1.0873x; 1.0873x over previous
#include <cuda_runtime.h>

#define NN 100000
#define EE 3200000
#define FIN 512
#define HID 16
#define CC 40
#define NB 391          // ceil(NN/256) scan blocks

// ---------------- scratch (static device globals) -----------------------------
__device__ float  g_deg[NN];
__device__ float  g_dis[NN];
__device__ int    g_cnt[NN];
__device__ int    g_base[NN];      // exclusive scan; mutated to row-ends by scatter
__device__ int    g_bsum[NB];
__device__ int    g_bsumx[NB];
__device__ unsigned long long g_wz[256 * 16];  // W1 k-pair-zipped: [k/2][f]
__device__ int2   g_edge[EE];      // dest-sorted (src, norm-as-int)
__device__ float4 g_h1[NN * 4];    // h1 = x@W1, [N,16] as [N,4] float4
__device__ float4 g_agg1[NN * 4];  // layer-1 aggregation
__device__ float4 g_agg2[NN * 4];  // layer-2 aggregation (16-dim, pre-W2)

#define FMA2(d, a, b) asm("fma.rn.f32x2 %0, %1, %2, %0;" : "+l"(d) : "l"(a), "l"(b))
#define ZIP(d, a, b)  asm("mov.b64 %0, {%1, %2};" : "=l"(d) : "f"(a), "f"(b))
#define CPA16(s, g)   asm volatile("cp.async.cg.shared.global [%0], [%1], 16;" :: "r"(s), "l"(g))
#define CP_COMMIT()   asm volatile("cp.async.commit_group;")
#define CP_WAIT(n)    asm volatile("cp.async.wait_group %0;" :: "n"(n))

// ---------------- zero init ---------------------------------------------------
__global__ void zero_kernel() {
    int i = blockIdx.x * blockDim.x + threadIdx.x;
    if (i < NN) { g_cnt[i] = 0; g_deg[i] = 0.f; }
}

// ---------------- in-degree count + weighted degree ---------------------------
__global__ void count_kernel(const int* __restrict__ ei,
                             const float* __restrict__ w) {
    int e = blockIdx.x * blockDim.x + threadIdx.x;
    if (e >= EE) return;
    int c = ei[EE + e];
    atomicAdd(&g_cnt[c], 1);
    atomicAdd(&g_deg[c], w[e]);
}

__global__ void dis_kernel() {
    int n = blockIdx.x * blockDim.x + threadIdx.x;
    if (n >= NN) return;
    float d = g_deg[n];
    g_dis[n] = (d > 0.f) ? rsqrtf(d) : 0.f;
}

// ---------------- W1 zip: g_wz[k2*16+f] = (W1[2k2][f], W1[2k2+1][f]) ----------
__global__ void wzip_kernel(const float* __restrict__ W1) {
    int i = blockIdx.x * blockDim.x + threadIdx.x;
    if (i >= 256 * 16) return;
    int k2 = i >> 4, f = i & 15;
    unsigned long long z;
    ZIP(z, W1[(2 * k2) * 16 + f], W1[(2 * k2 + 1) * 16 + f]);
    g_wz[i] = z;
}

// ---------------- 3-kernel exclusive scan of g_cnt -> g_base ------------------
__global__ void scanA_kernel() {
    __shared__ int s[256];
    int tid = threadIdx.x;
    int i = blockIdx.x * 256 + tid;
    int v = (i < NN) ? g_cnt[i] : 0;
    s[tid] = v;
    __syncthreads();
    for (int off = 1; off < 256; off <<= 1) {
        int t = (tid >= off) ? s[tid - off] : 0;
        __syncthreads();
        s[tid] += t;
        __syncthreads();
    }
    if (i < NN) g_base[i] = s[tid] - v;          // exclusive, intra-block
    if (tid == 255) g_bsum[blockIdx.x] = s[255];
}

__global__ void scanB_kernel() {
    __shared__ int s[512];
    int tid = threadIdx.x;
    int v = (tid < NB) ? g_bsum[tid] : 0;
    s[tid] = v;
    __syncthreads();
    for (int off = 1; off < 512; off <<= 1) {
        int t = (tid >= off) ? s[tid - off] : 0;
        __syncthreads();
        s[tid] += t;
        __syncthreads();
    }
    if (tid < NB) g_bsumx[tid] = s[tid] - v;     // exclusive block offsets
}

__global__ void scanC_kernel() {
    int i = blockIdx.x * blockDim.x + threadIdx.x;
    if (i < NN) g_base[i] += g_bsumx[i >> 8];
}

// ---------------- scatter edges (src, norm); bumps g_base to row-end ----------
__global__ void scatter_kernel(const int* __restrict__ ei,
                               const float* __restrict__ w) {
    int e = blockIdx.x * blockDim.x + threadIdx.x;
    if (e >= EE) return;
    int r = ei[e];
    int c = ei[EE + e];
    float nw = g_dis[r] * w[e] * g_dis[c];
    int pos = atomicAdd(&g_base[c], 1);
    g_edge[pos] = make_int2(r, __float_as_int(nw));
}

// ---------------- GEMM1 v5: h1 = x @ W1 ---------------------------------------
// 128 threads = 32 ng x 4 fg. Tile 256 nodes. Thread: 8 nodes x 4 f.
// Lane = 4*(ng&7)+fg -> the 4 fg lanes sharing an x address are adjacent
// (same smem wavefront -> broadcast free). Pitch-5-f4 rows: the 2 distinct
// ng per 8-lane phase hit distinct banks. W pre-zipped (k-pairs). 2-stage.
#define KCH 16
#define NCHUNK (FIN / KCH)   // 32
__global__ void __launch_bounds__(128) gemm1_kernel(const float* __restrict__ x) {
    __shared__ float4 xs[2][256 * 5];                 // [stage][node*5 + kq]
    __shared__ unsigned long long wsm[2][8 * 16];     // [stage][kp*16 + f]
    int tid = threadIdx.x;
    int warp = tid >> 5;
    int lane = tid & 31;
    int fg = lane & 3;                   // f = 4fg .. 4fg+3
    int ng = warp * 8 + (lane >> 2);     // 0..31
    int nodeBase = blockIdx.x * 256;

    // cp.async coords: 1024 x-f4 per stage, 128 threads -> 8 each
    int xnl = tid >> 2;                  // node-local base (plus 32*s)
    int xkq = tid & 3;

    unsigned long long acc[8][4];
#pragma unroll
    for (int i = 0; i < 8; ++i)
#pragma unroll
        for (int f = 0; f < 4; ++f) acc[i][f] = 0ull;

    const float* xg = x + (size_t)xkq * 4;

#define LOAD_CHUNK(kc, buf)                                                        \
    {                                                                              \
        int kb_ = (kc) * KCH;                                                      \
        _Pragma("unroll")                                                          \
        for (int s_ = 0; s_ < 8; ++s_) {                                           \
            int nl_ = xnl + 32 * s_;                                               \
            int node_ = nodeBase + nl_; if (node_ >= NN) node_ = NN - 1;           \
            unsigned d_ = (unsigned)__cvta_generic_to_shared(&xs[buf][nl_ * 5 + xkq]); \
            CPA16(d_, xg + (size_t)node_ * FIN + kb_);                             \
        }                                                                          \
        if (tid < 64) {                                                            \
            unsigned dw_ = (unsigned)__cvta_generic_to_shared(&wsm[buf][tid * 2]); \
            CPA16(dw_, &g_wz[(kc) * 128 + tid * 2]);                               \
        }                                                                          \
        CP_COMMIT();                                                               \
    }

    LOAD_CHUNK(0, 0)

    for (int kc = 0; kc < NCHUNK; ++kc) {
        int cur = kc & 1;
        if (kc + 1 < NCHUNK) {
            LOAD_CHUNK(kc + 1, cur ^ 1)
            CP_WAIT(1);
        } else {
            CP_WAIT(0);
        }
        __syncthreads();

#pragma unroll
        for (int kq = 0; kq < 4; ++kq) {
            // k-pairs kp0 = 2kq (k = 4kq,4kq+1), kp1 = 2kq+1 (k = 4kq+2,4kq+3)
            ulonglong2 w0a = *(const ulonglong2*)&wsm[cur][(2 * kq) * 16 + 4 * fg];
            ulonglong2 w0b = *(const ulonglong2*)&wsm[cur][(2 * kq) * 16 + 4 * fg + 2];
            ulonglong2 w1a = *(const ulonglong2*)&wsm[cur][(2 * kq + 1) * 16 + 4 * fg];
            ulonglong2 w1b = *(const ulonglong2*)&wsm[cur][(2 * kq + 1) * 16 + 4 * fg + 2];
#pragma unroll
            for (int i = 0; i < 8; ++i) {
                ulonglong2 xu = *(const ulonglong2*)&xs[cur][(ng + 32 * i) * 5 + kq];
                FMA2(acc[i][0], xu.x, w0a.x);
                FMA2(acc[i][1], xu.x, w0a.y);
                FMA2(acc[i][2], xu.x, w0b.x);
                FMA2(acc[i][3], xu.x, w0b.y);
                FMA2(acc[i][0], xu.y, w1a.x);
                FMA2(acc[i][1], xu.y, w1a.y);
                FMA2(acc[i][2], xu.y, w1b.x);
                FMA2(acc[i][3], xu.y, w1b.y);
            }
        }
        __syncthreads();
    }

    // fold k-split halves; one float4 store per node (f = 4fg..4fg+3)
#pragma unroll
    for (int i = 0; i < 8; ++i) {
        int node = nodeBase + ng + 32 * i;
        if (node >= NN) continue;
        float lo, hi;
        float4 o;
        asm("mov.b64 {%0, %1}, %2;" : "=f"(lo), "=f"(hi) : "l"(acc[i][0])); o.x = lo + hi;
        asm("mov.b64 {%0, %1}, %2;" : "=f"(lo), "=f"(hi) : "l"(acc[i][1])); o.y = lo + hi;
        asm("mov.b64 {%0, %1}, %2;" : "=f"(lo), "=f"(hi) : "l"(acc[i][2])); o.z = lo + hi;
        asm("mov.b64 {%0, %1}, %2;" : "=f"(lo), "=f"(hi) : "l"(acc[i][3])); o.w = lo + hi;
        g_h1[node * 4 + fg] = o;
    }
}

// ---------------- gather-reduce propagation (warp per node, no atomics) -------
__global__ void __launch_bounds__(256) gather1_kernel() {
    int node = (blockIdx.x * 256 + threadIdx.x) >> 5;
    if (node >= NN) return;
    int lane = threadIdx.x & 31;
    int q = lane & 3;
    int es = lane >> 2;
    int b0 = node ? g_base[node - 1] : 0;
    int b1e = g_base[node];
    float4 acc = make_float4(0.f, 0.f, 0.f, 0.f);
    for (int i = b0 + es; i < b1e; i += 8) {
        int2 ew = g_edge[i];
        float nw = __int_as_float(ew.y);
        float4 v = g_h1[ew.x * 4 + q];
        acc.x += nw * v.x; acc.y += nw * v.y;
        acc.z += nw * v.z; acc.w += nw * v.w;
    }
#pragma unroll
    for (int m = 16; m >= 4; m >>= 1) {
        acc.x += __shfl_xor_sync(0xffffffffu, acc.x, m);
        acc.y += __shfl_xor_sync(0xffffffffu, acc.y, m);
        acc.z += __shfl_xor_sync(0xffffffffu, acc.z, m);
        acc.w += __shfl_xor_sync(0xffffffffu, acc.w, m);
    }
    if (es == 0) g_agg1[node * 4 + q] = acc;
}

// layer 2: gather relu(agg1[src] + b1) * norm
__global__ void __launch_bounds__(256) gather2_kernel(const float* __restrict__ b1) {
    int node = (blockIdx.x * 256 + threadIdx.x) >> 5;
    if (node >= NN) return;
    int lane = threadIdx.x & 31;
    int q = lane & 3;
    int es = lane >> 2;
    float4 b = ((const float4*)b1)[q];
    int b0 = node ? g_base[node - 1] : 0;
    int b1e = g_base[node];
    float4 acc = make_float4(0.f, 0.f, 0.f, 0.f);
    for (int i = b0 + es; i < b1e; i += 8) {
        int2 ew = g_edge[i];
        float nw = __int_as_float(ew.y);
        float4 v = g_agg1[ew.x * 4 + q];
        acc.x += nw * fmaxf(v.x + b.x, 0.f);
        acc.y += nw * fmaxf(v.y + b.y, 0.f);
        acc.z += nw * fmaxf(v.z + b.z, 0.f);
        acc.w += nw * fmaxf(v.w + b.w, 0.f);
    }
#pragma unroll
    for (int m = 16; m >= 4; m >>= 1) {
        acc.x += __shfl_xor_sync(0xffffffffu, acc.x, m);
        acc.y += __shfl_xor_sync(0xffffffffu, acc.y, m);
        acc.z += __shfl_xor_sync(0xffffffffu, acc.z, m);
        acc.w += __shfl_xor_sync(0xffffffffu, acc.w, m);
    }
    if (es == 0) g_agg2[node * 4 + q] = acc;
}

// ---------------- epilogue: out = log_softmax(agg2 @ W2 + b2) -----------------
__global__ void __launch_bounds__(256) out_kernel(const float* __restrict__ W2,
                                                  const float* __restrict__ b2,
                                                  float* __restrict__ out) {
    __shared__ float w2s[HID * CC];
    __shared__ float b2s[CC];
    int tid = threadIdx.x;
    for (int i = tid; i < HID * CC; i += 256) w2s[i] = W2[i];
    if (tid < CC) b2s[tid] = b2[tid];
    __syncthreads();

    int n = blockIdx.x * blockDim.x + tid;
    if (n >= NN) return;

    float a[16];
    float4* ap = (float4*)a;
    ap[0] = g_agg2[n * 4 + 0];
    ap[1] = g_agg2[n * 4 + 1];
    ap[2] = g_agg2[n * 4 + 2];
    ap[3] = g_agg2[n * 4 + 3];

    float logit[CC];
    float mx = -1e30f;
#pragma unroll
    for (int j = 0; j < CC; ++j) {
        float s = b2s[j];
#pragma unroll
        for (int i = 0; i < 16; ++i) s += a[i] * w2s[i * CC + j];
        logit[j] = s;
        mx = fmaxf(mx, s);
    }
    float sum = 0.f;
#pragma unroll
    for (int j = 0; j < CC; ++j) sum += expf(logit[j] - mx);
    float lse = mx + logf(sum);
#pragma unroll
    for (int j = 0; j < CC; ++j) out[(size_t)n * CC + j] = logit[j] - lse;
}

// ---------------- launch ------------------------------------------------------
extern "C" void kernel_launch(void* const* d_in, const int* in_sizes, int n_in,
                              void* d_out, int out_size) {
    const float* x  = (const float*)d_in[0];
    const int*   ei = (const int*)d_in[1];
    const float* w  = (const float*)d_in[2];
    const float* W1 = (const float*)d_in[3];
    const float* b1 = (const float*)d_in[4];
    const float* W2 = (const float*)d_in[5];
    const float* b2 = (const float*)d_in[6];
    float*       out = (float*)d_out;

    zero_kernel<<<(NN + 255) / 256, 256>>>();
    count_kernel<<<(EE + 255) / 256, 256>>>(ei, w);
    wzip_kernel<<<16, 256>>>(W1);
    gemm1_kernel<<<(NN + 255) / 256, 128>>>(x);      // 4th launch -> profiled
    dis_kernel<<<(NN + 255) / 256, 256>>>();
    scanA_kernel<<<NB, 256>>>();
    scanB_kernel<<<1, 512>>>();
    scanC_kernel<<<(NN + 255) / 256, 256>>>();
    scatter_kernel<<<(EE + 255) / 256, 256>>>(ei, w);
    gather1_kernel<<<(NN * 32 + 255) / 256, 256>>>();
    gather2_kernel<<<(NN * 32 + 255) / 256, 256>>>(b1);
    out_kernel<<<(NN + 255) / 256, 256>>>(W2, b2, out);
}